// round 5
// baseline (speedup 1.0000x reference)
#include <cuda_runtime.h>
#include <stdint.h>

#define NDOF_MAX 1000000

__device__ float g_u1[NDOF_MAX];

// Kernel A: u1[bc[i]] = w[i] * u[bc[i]], 4 DOFs/thread (bc is arange -> coalesced).
__global__ void prep_kernel(const float* __restrict__ u,
                            const float4* __restrict__ w4,
                            const int4* __restrict__ bc4,
                            int n4)
{
    int i = blockIdx.x * blockDim.x + threadIdx.x;
    if (i < n4) {
        int4 b = bc4[i];
        float4 w = w4[i];
        g_u1[b.x] = w.x * __ldg(&u[b.x]);
        g_u1[b.y] = w.y * __ldg(&u[b.y]);
        g_u1[b.z] = w.z * __ldg(&u[b.z]);
        g_u1[b.w] = w.w * __ldg(&u[b.w]);
    }
}

// Kernel B: 1 element/thread. Load order: ke first (independent of idx,
// 16 front-batched LDG.128), then edof, then gathers, then FMA + RED.
// launch_bounds(256, 6) caps regs (~40) -> 48 warps/SM.
__global__ void __launch_bounds__(256, 6) assemble_kernel(
    const int* __restrict__ edof,           // [E,8] int32
    const float* __restrict__ ke,           // [E,8,8]
    float* __restrict__ F,                  // [NDOF]
    int E)
{
    int e = blockIdx.x * blockDim.x + threadIdx.x;
    if (e >= E) return;

    // 1) ke rows: 16 independent float4 loads, issued before anything else.
    const float4* kv = reinterpret_cast<const float4*>(ke + (size_t)e * 64);
    float4 k[16];
    #pragma unroll
    for (int i = 0; i < 16; i++) k[i] = kv[i];

    // 2) element DOF indices: two int4 loads (32 B, coalesced)
    const int4* erow = reinterpret_cast<const int4*>(edof + (size_t)e * 8);
    int4 i0 = erow[0];
    int4 i1 = erow[1];
    int idx[8] = { i0.x, i0.y, i0.z, i0.w, i1.x, i1.y, i1.z, i1.w };

    // 3) gathers (L2-resident u1, scattered sectors)
    float ue[8];
    #pragma unroll
    for (int j = 0; j < 8; j++) ue[j] = __ldg(&g_u1[idx[j]]);

    // 4) matvec + fire-and-forget scatter-add
    #pragma unroll
    for (int i = 0; i < 8; i++) {
        float4 a = k[i * 2 + 0];
        float4 b = k[i * 2 + 1];
        float s = a.x*ue[0] + a.y*ue[1] + a.z*ue[2] + a.w*ue[3]
                + b.x*ue[4] + b.y*ue[5] + b.z*ue[6] + b.w*ue[7];
        atomicAdd(&F[idx[i]], s);
    }
}

extern "C" void kernel_launch(void* const* d_in, const int* in_sizes, int n_in,
                              void* d_out, int out_size)
{
    const float* u    = (const float*)d_in[0];
    const float* w    = (const float*)d_in[1];
    const int*   bc   = (const int*)d_in[2];
    const int*   edof = (const int*)d_in[3];
    const float* ke   = (const float*)d_in[4];
    float* F = (float*)d_out;

    int ndof = in_sizes[0];            // 2*NNODE (divisible by 4)
    int E    = in_sizes[3] / 8;        // NELEM

    // Zero output (graph-capturable async memset) concurrent-ish with prep.
    cudaMemsetAsync(F, 0, (size_t)ndof * sizeof(float));

    int n4 = ndof / 4;
    prep_kernel<<<(n4 + 255) / 256, 256>>>(
        u, (const float4*)w, (const int4*)bc, n4);

    assemble_kernel<<<(E + 255) / 256, 256>>>(edof, ke, F, E);
}

// round 6
// speedup vs baseline: 1.0028x; 1.0028x over previous
#include <cuda_runtime.h>
#include <stdint.h>

#define NDOF_MAX 1000000

__device__ float g_u1[NDOF_MAX];

// Kernel A: u1[bc[i]] = w[i] * u[bc[i]], 4 DOFs/thread (bc is arange -> coalesced).
__global__ void prep_kernel(const float* __restrict__ u,
                            const float4* __restrict__ w4,
                            const int4* __restrict__ bc4,
                            int n4)
{
    int i = blockIdx.x * blockDim.x + threadIdx.x;
    if (i < n4) {
        int4 b = bc4[i];
        float4 w = w4[i];
        g_u1[b.x] = w.x * __ldg(&u[b.x]);
        g_u1[b.y] = w.y * __ldg(&u[b.y]);
        g_u1[b.z] = w.z * __ldg(&u[b.z]);
        g_u1[b.w] = w.w * __ldg(&u[b.w]);
    }
}

// Kernel B: 1 element/thread. Load order: ke first (independent of idx,
// 16 front-batched LDG.128), then edof, then gathers, then FMA + RED.
// launch_bounds(256, 6) caps regs (~40) -> 48 warps/SM.
__global__ void __launch_bounds__(256, 6) assemble_kernel(
    const int* __restrict__ edof,           // [E,8] int32
    const float* __restrict__ ke,           // [E,8,8]
    float* __restrict__ F,                  // [NDOF]
    int E)
{
    int e = blockIdx.x * blockDim.x + threadIdx.x;
    if (e >= E) return;

    // 1) ke rows: 16 independent float4 loads, issued before anything else.
    const float4* kv = reinterpret_cast<const float4*>(ke + (size_t)e * 64);
    float4 k[16];
    #pragma unroll
    for (int i = 0; i < 16; i++) k[i] = kv[i];

    // 2) element DOF indices: two int4 loads (32 B, coalesced)
    const int4* erow = reinterpret_cast<const int4*>(edof + (size_t)e * 8);
    int4 i0 = erow[0];
    int4 i1 = erow[1];
    int idx[8] = { i0.x, i0.y, i0.z, i0.w, i1.x, i1.y, i1.z, i1.w };

    // 3) gathers (L2-resident u1, scattered sectors)
    float ue[8];
    #pragma unroll
    for (int j = 0; j < 8; j++) ue[j] = __ldg(&g_u1[idx[j]]);

    // 4) matvec + fire-and-forget scatter-add
    #pragma unroll
    for (int i = 0; i < 8; i++) {
        float4 a = k[i * 2 + 0];
        float4 b = k[i * 2 + 1];
        float s = a.x*ue[0] + a.y*ue[1] + a.z*ue[2] + a.w*ue[3]
                + b.x*ue[4] + b.y*ue[5] + b.z*ue[6] + b.w*ue[7];
        atomicAdd(&F[idx[i]], s);
    }
}

extern "C" void kernel_launch(void* const* d_in, const int* in_sizes, int n_in,
                              void* d_out, int out_size)
{
    const float* u    = (const float*)d_in[0];
    const float* w    = (const float*)d_in[1];
    const int*   bc   = (const int*)d_in[2];
    const int*   edof = (const int*)d_in[3];
    const float* ke   = (const float*)d_in[4];
    float* F = (float*)d_out;

    int ndof = in_sizes[0];            // 2*NNODE (divisible by 4)
    int E    = in_sizes[3] / 8;        // NELEM

    // Zero output (graph-capturable async memset) concurrent-ish with prep.
    cudaMemsetAsync(F, 0, (size_t)ndof * sizeof(float));

    int n4 = ndof / 4;
    prep_kernel<<<(n4 + 255) / 256, 256>>>(
        u, (const float4*)w, (const int4*)bc, n4);

    assemble_kernel<<<(E + 255) / 256, 256>>>(edof, ke, F, E);
}

// round 7
// speedup vs baseline: 1.0299x; 1.0270x over previous
#include <cuda_runtime.h>
#include <stdint.h>

#define NDOF_MAX 1000000

__device__ float g_u1[NDOF_MAX];

// Kernel A: u1[i] = w[i] * u[bc[i]] (bc is arange -> coalesced), and F[i] = 0.
__global__ void prep_kernel(const float* __restrict__ u,
                            const float4* __restrict__ w4,
                            const int4* __restrict__ bc4,
                            float4* __restrict__ F4,
                            int n4)
{
    int i = blockIdx.x * blockDim.x + threadIdx.x;
    if (i < n4) {
        int4 b = bc4[i];
        float4 w = w4[i];
        g_u1[b.x] = w.x * __ldg(&u[b.x]);
        g_u1[b.y] = w.y * __ldg(&u[b.y]);
        g_u1[b.z] = w.z * __ldg(&u[b.z]);
        g_u1[b.w] = w.w * __ldg(&u[b.w]);
        F4[i] = make_float4(0.f, 0.f, 0.f, 0.f);
    }
}

// Kernel B: grid-stride persistent loop, balanced waves (grid = 148*6 CTAs).
// Per iteration: ke first (16 independent LDG.128), then edof, gathers, FMA+RED.
#define NCTA 888   // 148 SMs * 6 CTAs/SM

__global__ void __launch_bounds__(256, 6) assemble_kernel(
    const int* __restrict__ edof,           // [E,8] int32
    const float* __restrict__ ke,           // [E,8,8]
    float* __restrict__ F,                  // [NDOF]
    int E)
{
    const int stride = NCTA * 256;
    for (int e = blockIdx.x * 256 + threadIdx.x; e < E; e += stride) {
        // 1) ke rows: 16 independent float4 loads, issued first (max MLP).
        const float4* kv = reinterpret_cast<const float4*>(ke + (size_t)e * 64);
        float4 k[16];
        #pragma unroll
        for (int i = 0; i < 16; i++) k[i] = kv[i];

        // 2) element DOF indices (32 B coalesced)
        const int4* erow = reinterpret_cast<const int4*>(edof + (size_t)e * 8);
        int4 i0 = erow[0];
        int4 i1 = erow[1];
        int idx[8] = { i0.x, i0.y, i0.z, i0.w, i1.x, i1.y, i1.z, i1.w };

        // 3) gathers (L2-resident u1)
        float ue[8];
        #pragma unroll
        for (int j = 0; j < 8; j++) ue[j] = __ldg(&g_u1[idx[j]]);

        // 4) matvec + fire-and-forget scatter-add
        #pragma unroll
        for (int i = 0; i < 8; i++) {
            float4 a = k[i * 2 + 0];
            float4 b = k[i * 2 + 1];
            float s = a.x*ue[0] + a.y*ue[1] + a.z*ue[2] + a.w*ue[3]
                    + b.x*ue[4] + b.y*ue[5] + b.z*ue[6] + b.w*ue[7];
            atomicAdd(&F[idx[i]], s);
        }
    }
}

extern "C" void kernel_launch(void* const* d_in, const int* in_sizes, int n_in,
                              void* d_out, int out_size)
{
    const float* u    = (const float*)d_in[0];
    const float* w    = (const float*)d_in[1];
    const int*   bc   = (const int*)d_in[2];
    const int*   edof = (const int*)d_in[3];
    const float* ke   = (const float*)d_in[4];
    float* F = (float*)d_out;

    int ndof = in_sizes[0];            // 2*NNODE (divisible by 4)
    int E    = in_sizes[3] / 8;        // NELEM

    int n4 = ndof / 4;
    prep_kernel<<<(n4 + 255) / 256, 256>>>(
        u, (const float4*)w, (const int4*)bc, (float4*)F, n4);

    assemble_kernel<<<NCTA, 256>>>(edof, ke, F, E);
}

// round 8
// speedup vs baseline: 1.0751x; 1.0438x over previous
#include <cuda_runtime.h>
#include <stdint.h>

#define NDOF_MAX 1000000

__device__ float g_u1[NDOF_MAX];

// Kernel A: u1[bc[i]] = w[i] * u[bc[i]] (bc is arange -> coalesced), F[i] = 0.
__global__ void prep_kernel(const float* __restrict__ u,
                            const float4* __restrict__ w4,
                            const int4* __restrict__ bc4,
                            float4* __restrict__ F4,
                            int n4)
{
    int i = blockIdx.x * blockDim.x + threadIdx.x;
    if (i < n4) {
        int4 b = bc4[i];
        float4 w = w4[i];
        g_u1[b.x] = w.x * __ldg(&u[b.x]);
        g_u1[b.y] = w.y * __ldg(&u[b.y]);
        g_u1[b.z] = w.z * __ldg(&u[b.z]);
        g_u1[b.w] = w.w * __ldg(&u[b.w]);
        F4[i] = make_float4(0.f, 0.f, 0.f, 0.f);
    }
}

// Split-gather: one logical gather issued as 4 predicated LDGs (8 active
// lanes each, selected by quarter-warp id q). Forces the 32 scattered
// sector-wavefronts to originate from 4 different LDG instructions so the
// L1tex replay engine processes them at the cross-LDG rate (~1.0 cyc/wf)
// instead of the within-LDG rate (~2.07 cyc/wf). Inline asm prevents ptxas
// from merging the four loads back into one.
__device__ __forceinline__ float gather_q4(const float* p, int q)
{
    float v;
    asm volatile(
        "{\n\t"
        ".reg .pred q0, q1, q2, q3;\n\t"
        "setp.eq.u32 q0, %1, 0;\n\t"
        "setp.eq.u32 q1, %1, 1;\n\t"
        "setp.eq.u32 q2, %1, 2;\n\t"
        "setp.eq.u32 q3, %1, 3;\n\t"
        "@q0 ld.global.nc.f32 %0, [%2];\n\t"
        "@q1 ld.global.nc.f32 %0, [%2];\n\t"
        "@q2 ld.global.nc.f32 %0, [%2];\n\t"
        "@q3 ld.global.nc.f32 %0, [%2];\n\t"
        "}"
        : "=f"(v) : "r"(q), "l"(p));
    return v;
}

// Kernel B: flat grid (best measured config), 1 elem/thread, ke loads first,
// split gathers, RED scatter.
__global__ void __launch_bounds__(256, 6) assemble_kernel(
    const int* __restrict__ edof,           // [E,8] int32
    const float* __restrict__ ke,           // [E,8,8]
    float* __restrict__ F,                  // [NDOF]
    int E)
{
    int e = blockIdx.x * blockDim.x + threadIdx.x;
    if (e >= E) return;

    const int q = (threadIdx.x >> 3) & 3;   // quarter-warp id

    // 1) ke rows: 16 independent float4 loads issued first (max MLP).
    const float4* kv = reinterpret_cast<const float4*>(ke + (size_t)e * 64);
    float4 k[16];
    #pragma unroll
    for (int i = 0; i < 16; i++) k[i] = kv[i];

    // 2) element DOF indices (32 B coalesced)
    const int4* erow = reinterpret_cast<const int4*>(edof + (size_t)e * 8);
    int4 i0 = erow[0];
    int4 i1 = erow[1];
    int idx[8] = { i0.x, i0.y, i0.z, i0.w, i1.x, i1.y, i1.z, i1.w };

    // 3) gathers, quarter-warp split
    float ue[8];
    #pragma unroll
    for (int j = 0; j < 8; j++) ue[j] = gather_q4(&g_u1[idx[j]], q);

    // 4) matvec + fire-and-forget scatter-add
    #pragma unroll
    for (int i = 0; i < 8; i++) {
        float4 a = k[i * 2 + 0];
        float4 b = k[i * 2 + 1];
        float s = a.x*ue[0] + a.y*ue[1] + a.z*ue[2] + a.w*ue[3]
                + b.x*ue[4] + b.y*ue[5] + b.z*ue[6] + b.w*ue[7];
        atomicAdd(&F[idx[i]], s);
    }
}

extern "C" void kernel_launch(void* const* d_in, const int* in_sizes, int n_in,
                              void* d_out, int out_size)
{
    const float* u    = (const float*)d_in[0];
    const float* w    = (const float*)d_in[1];
    const int*   bc   = (const int*)d_in[2];
    const int*   edof = (const int*)d_in[3];
    const float* ke   = (const float*)d_in[4];
    float* F = (float*)d_out;

    int ndof = in_sizes[0];            // 2*NNODE (divisible by 4)
    int E    = in_sizes[3] / 8;        // NELEM

    int n4 = ndof / 4;
    prep_kernel<<<(n4 + 255) / 256, 256>>>(
        u, (const float4*)w, (const int4*)bc, (float4*)F, n4);

    assemble_kernel<<<(E + 255) / 256, 256>>>(edof, ke, F, E);
}